// round 1
// baseline (speedup 1.0000x reference)
#include <cuda_runtime.h>

#define NB 2048
#define NV 5023
#define NC 15069     // NV*3
#define CPAD 15168   // 79 * 192
#define KF 88        // 50 expr + 36 pf + 1 bias + 1 pad

__device__ float g_W[KF * CPAD];    // [l][c]  K-major packed weights
__device__ float g_X[KF * NB];      // [l][b]  per-batch features
__device__ float g_A[NB * 5 * 12];  // [b][j][3x4] relative transforms
__device__ float g_JS[15 * 51];     // [j*3+k][l]  (l=50 is v_template part)

// ---------------------------------------------------------------- pack W
__global__ void packW_kernel(const float* __restrict__ vt,
                             const float* __restrict__ SD,
                             const float* __restrict__ PD) {
    int c = blockIdx.x * blockDim.x + threadIdx.x;
    if (c >= CPAD) return;
    bool valid = c < NC;
    #pragma unroll 1
    for (int l = 0; l < 50; l++)
        g_W[l * CPAD + c] = valid ? SD[c * 150 + 100 + l] : 0.f;
    #pragma unroll 1
    for (int l = 0; l < 36; l++)
        g_W[(50 + l) * CPAD + c] = valid ? PD[l * NC + c] : 0.f;
    g_W[86 * CPAD + c] = valid ? vt[c] : 0.f;
    g_W[87 * CPAD + c] = 0.f;
}

// -------------------------------------------- J_regressor contractions
__global__ void jpre_kernel(const float* __restrict__ Jreg,
                            const float* __restrict__ vt,
                            const float* __restrict__ SD) {
    int gw = (blockIdx.x * blockDim.x + threadIdx.x) >> 5;
    int lane = threadIdx.x & 31;
    if (gw >= 765) return;
    int e = gw / 51, l = gw % 51;
    int j = e / 3, k = e % 3;
    float acc = 0.f;
    for (int v = lane; v < NV; v += 32) {
        float w = Jreg[j * NV + v];
        float s = (l < 50) ? SD[(v * 3 + k) * 150 + 100 + l] : vt[v * 3 + k];
        acc = fmaf(w, s, acc);
    }
    #pragma unroll
    for (int o = 16; o; o >>= 1) acc += __shfl_xor_sync(0xffffffffu, acc, o);
    if (lane == 0) g_JS[e * 51 + l] = acc;
}

// ------------------------------------- per-batch: rodrigues, FK, A, X
__global__ void batch_kernel(const float* __restrict__ expr,
                             const float* __restrict__ pose,
                             float* __restrict__ out_pf,
                             float* __restrict__ out_A) {
    int b = blockIdx.x * blockDim.x + threadIdx.x;
    if (b >= NB) return;

    // joints[j][k] via precomputed contraction; also stream expr into g_X
    float jnt[15];
    #pragma unroll
    for (int e = 0; e < 15; e++) jnt[e] = g_JS[e * 51 + 50];
    #pragma unroll 1
    for (int l = 0; l < 50; l++) {
        float ev = expr[b * 50 + l];
        g_X[l * NB + b] = ev;
        #pragma unroll
        for (int e = 0; e < 15; e++) jnt[e] = fmaf(ev, g_JS[e * 51 + l], jnt[e]);
    }
    g_X[86 * NB + b] = 1.f;   // bias row -> v_template
    g_X[87 * NB + b] = 0.f;   // pad

    // Rodrigues for 5 joints (mirrors reference: angle uses rot_vec + 1e-8)
    float R[5][9];
    #pragma unroll
    for (int j = 0; j < 5; j++) {
        float x = pose[b * 15 + j * 3 + 0];
        float y = pose[b * 15 + j * 3 + 1];
        float z = pose[b * 15 + j * 3 + 2];
        float ax = x + 1e-8f, ay = y + 1e-8f, az = z + 1e-8f;
        float ang = sqrtf(ax * ax + ay * ay + az * az);
        float inv = 1.f / ang;
        float rx = x * inv, ry = y * inv, rz = z * inv;
        float s = sinf(ang), cth = cosf(ang), t = 1.f - cth;
        float s2 = rx * rx + ry * ry + rz * rz;
        R[j][0] = 1.f + t * (rx * rx - s2);
        R[j][1] = -s * rz + t * rx * ry;
        R[j][2] =  s * ry + t * rx * rz;
        R[j][3] =  s * rz + t * rx * ry;
        R[j][4] = 1.f + t * (ry * ry - s2);
        R[j][5] = -s * rx + t * ry * rz;
        R[j][6] = -s * ry + t * rx * rz;
        R[j][7] =  s * rx + t * ry * rz;
        R[j][8] = 1.f + t * (rz * rz - s2);
    }

    // pose_feature (joints 1..4, R - I), to g_X rows 50..85 and to output
    #pragma unroll
    for (int j = 1; j < 5; j++) {
        #pragma unroll
        for (int idx = 0; idx < 9; idx++) {
            int m = (j - 1) * 9 + idx;
            float v = R[j][idx] - ((idx == 0 || idx == 4 || idx == 8) ? 1.f : 0.f);
            g_X[(50 + m) * NB + b] = v;
            out_pf[b * 36 + m] = v;
        }
    }

    // FK: parents = [-1,0,1,1,1]; G[j] = 3x4 [Rg|tg]
    float G[5][12];
    #pragma unroll
    for (int p = 0; p < 3; p++) {
        G[0][p * 4 + 0] = R[0][p * 3 + 0];
        G[0][p * 4 + 1] = R[0][p * 3 + 1];
        G[0][p * 4 + 2] = R[0][p * 3 + 2];
        G[0][p * 4 + 3] = jnt[p];
    }
    #pragma unroll
    for (int j = 1; j < 5; j++) {
        const int par = (j == 1) ? 0 : 1;
        float t0 = jnt[j * 3 + 0] - jnt[par * 3 + 0];
        float t1 = jnt[j * 3 + 1] - jnt[par * 3 + 1];
        float t2 = jnt[j * 3 + 2] - jnt[par * 3 + 2];
        #pragma unroll
        for (int p = 0; p < 3; p++) {
            float g0 = G[par][p * 4 + 0], g1 = G[par][p * 4 + 1];
            float g2 = G[par][p * 4 + 2], g3 = G[par][p * 4 + 3];
            #pragma unroll
            for (int q = 0; q < 3; q++)
                G[j][p * 4 + q] = g0 * R[j][q] + g1 * R[j][3 + q] + g2 * R[j][6 + q];
            G[j][p * 4 + 3] = g0 * t0 + g1 * t1 + g2 * t2 + g3;
        }
    }

    // A = G with translation corrected by -Rg * joint; write scratch + output
    #pragma unroll
    for (int j = 0; j < 5; j++) {
        #pragma unroll
        for (int p = 0; p < 3; p++) {
            float r0 = G[j][p * 4 + 0], r1 = G[j][p * 4 + 1], r2 = G[j][p * 4 + 2];
            float ta = G[j][p * 4 + 3] -
                       (r0 * jnt[j * 3 + 0] + r1 * jnt[j * 3 + 1] + r2 * jnt[j * 3 + 2]);
            int gb = b * 60 + j * 12 + p * 4;
            g_A[gb + 0] = r0; g_A[gb + 1] = r1; g_A[gb + 2] = r2; g_A[gb + 3] = ta;
            int ob = b * 80 + j * 16 + p * 4;
            out_A[ob + 0] = r0; out_A[ob + 1] = r1; out_A[ob + 2] = r2; out_A[ob + 3] = ta;
        }
        int ob = b * 80 + j * 16 + 12;
        out_A[ob + 0] = 0.f; out_A[ob + 1] = 0.f; out_A[ob + 2] = 0.f; out_A[ob + 3] = 1.f;
    }
}

// ----------------------------------- main GEMM (X·W) + fused LBS skinning
// Block tile: 64 batches x 192 components (64 vertices). 256 threads.
// Thread: by = tid>>5 picks 8 batches, cx = tid&31 picks 2 vertices (6 comps).
__global__ __launch_bounds__(256, 2)
void skin_kernel(const float* __restrict__ lbs, float* __restrict__ out) {
    __shared__ float sh[5632];                 // 22.5 KB, reused across phases
    float* Xs = sh;                            // [22][64]
    float* Ws = sh + 22 * 64;                  // [22][192]

    const int tid = threadIdx.x;
    const int cx = tid & 31;
    const int by = tid >> 5;
    const int bBase = blockIdx.y * 64;
    const int cBase = blockIdx.x * 192;
    const int vBase = blockIdx.x * 64;

    float acc[8][6];
    #pragma unroll
    for (int i = 0; i < 8; i++)
        #pragma unroll
        for (int j = 0; j < 6; j++) acc[i][j] = 0.f;

    #pragma unroll 1
    for (int ch = 0; ch < 4; ch++) {
        const int k0 = ch * 22;
        #pragma unroll 1
        for (int i = tid; i < 22 * 64; i += 256) {
            int l = i >> 6, bb = i & 63;
            Xs[i] = g_X[(k0 + l) * NB + bBase + bb];
        }
        #pragma unroll 1
        for (int i = tid; i < 22 * 192; i += 256) {
            int l = i / 192, cc = i - l * 192;
            Ws[i] = g_W[(k0 + l) * CPAD + cBase + cc];
        }
        __syncthreads();
        #pragma unroll
        for (int k = 0; k < 22; k++) {
            const float4* x4 = reinterpret_cast<const float4*>(Xs + k * 64 + by * 8);
            float4 xa = x4[0], xb = x4[1];
            const float2* w2 = reinterpret_cast<const float2*>(Ws + k * 192 + cx * 6);
            float2 wa = w2[0], wb = w2[1], wc = w2[2];
            float xv[8] = {xa.x, xa.y, xa.z, xa.w, xb.x, xb.y, xb.z, xb.w};
            float wv[6] = {wa.x, wa.y, wb.x, wb.y, wc.x, wc.y};
            #pragma unroll
            for (int i = 0; i < 8; i++)
                #pragma unroll
                for (int j = 0; j < 6; j++)
                    acc[i][j] = fmaf(xv[i], wv[j], acc[i][j]);
        }
        __syncthreads();
    }

    // ---- skinning epilogue (smem reused) ----
    float* As = sh;                  // [64][60]
    float* wjs = sh + 64 * 60;       // [64][6]
    #pragma unroll 1
    for (int i = tid; i < 64 * 60; i += 256)
        As[i] = g_A[(bBase + (i / 60)) * 60 + (i - (i / 60) * 60)];
    #pragma unroll 1
    for (int i = tid; i < 64 * 5; i += 256) {
        int vv = i / 5, jj = i - vv * 5;
        int v = vBase + vv;
        wjs[vv * 6 + jj] = (v < NV) ? lbs[v * 5 + jj] : 0.f;
    }
    __syncthreads();

    float w[2][5];
    #pragma unroll
    for (int jj = 0; jj < 5; jj++) {
        w[0][jj] = wjs[(cx * 2 + 0) * 6 + jj];
        w[1][jj] = wjs[(cx * 2 + 1) * 6 + jj];
    }
    const int v0 = vBase + cx * 2;

    #pragma unroll
    for (int i = 0; i < 8; i++) {
        const int b = bBase + by * 8 + i;
        const float4* Ab4 = reinterpret_cast<const float4*>(As + (by * 8 + i) * 60);
        float o[6];
        #pragma unroll
        for (int vl = 0; vl < 2; vl++) {
            float4 M0 = make_float4(0.f, 0.f, 0.f, 0.f), M1 = M0, M2 = M0;
            #pragma unroll
            for (int j = 0; j < 5; j++) {
                float wv = w[vl][j];
                float4 a0 = Ab4[j * 3 + 0], a1 = Ab4[j * 3 + 1], a2 = Ab4[j * 3 + 2];
                M0.x = fmaf(wv, a0.x, M0.x); M0.y = fmaf(wv, a0.y, M0.y);
                M0.z = fmaf(wv, a0.z, M0.z); M0.w = fmaf(wv, a0.w, M0.w);
                M1.x = fmaf(wv, a1.x, M1.x); M1.y = fmaf(wv, a1.y, M1.y);
                M1.z = fmaf(wv, a1.z, M1.z); M1.w = fmaf(wv, a1.w, M1.w);
                M2.x = fmaf(wv, a2.x, M2.x); M2.y = fmaf(wv, a2.y, M2.y);
                M2.z = fmaf(wv, a2.z, M2.z); M2.w = fmaf(wv, a2.w, M2.w);
            }
            float px = acc[i][vl * 3 + 0], py = acc[i][vl * 3 + 1], pz = acc[i][vl * 3 + 2];
            o[vl * 3 + 0] = fmaf(M0.x, px, fmaf(M0.y, py, fmaf(M0.z, pz, M0.w)));
            o[vl * 3 + 1] = fmaf(M1.x, px, fmaf(M1.y, py, fmaf(M1.z, pz, M1.w)));
            o[vl * 3 + 2] = fmaf(M2.x, px, fmaf(M2.y, py, fmaf(M2.z, pz, M2.w)));
        }
        size_t ob = ((size_t)b * NV + v0) * 3;
        if (v0 + 1 < NV) {
            #pragma unroll
            for (int t = 0; t < 6; t++) out[ob + t] = o[t];
        } else if (v0 < NV) {
            out[ob + 0] = o[0]; out[ob + 1] = o[1]; out[ob + 2] = o[2];
        }
    }
}

// ---------------------------------------------------------------- launch
extern "C" void kernel_launch(void* const* d_in, const int* in_sizes, int n_in,
                              void* d_out, int out_size) {
    const float* expr = (const float*)d_in[0];  // [2048,50]
    const float* pose = (const float*)d_in[1];  // [2048,15]
    const float* vt   = (const float*)d_in[2];  // [5023,3]
    const float* SD   = (const float*)d_in[3];  // [5023,3,150]
    const float* PD   = (const float*)d_in[4];  // [36,15069]
    const float* Jreg = (const float*)d_in[5];  // [5,5023]
    const float* lbs  = (const float*)d_in[6];  // [5023,5]

    float* out       = (float*)d_out;
    float* out_verts = out;                              // [B,V,3]
    float* out_pf    = out + (size_t)NB * NV * 3;        // [B,36]
    float* out_A     = out_pf + (size_t)NB * 36;         // [B,5,4,4]

    packW_kernel<<<(CPAD + 255) / 256, 256>>>(vt, SD, PD);
    jpre_kernel<<<(765 * 32 + 255) / 256, 256>>>(Jreg, vt, SD);
    batch_kernel<<<NB / 128, 128>>>(expr, pose, out_pf, out_A);
    dim3 grid(79, 32);
    skin_kernel<<<grid, 256>>>(lbs, out_verts);
}

// round 3
// speedup vs baseline: 2.0622x; 2.0622x over previous
#include <cuda_runtime.h>
#include <cuda_bf16.h>
#include <cstdint>

#define NB 2048
#define NV 5023
#define NC 15069          // NV*3
#define CPAD 15072        // 157 * 96
#define KU4 12            // uint4 per packed row (96 bf16 = 192B)

// ---------------- device scratch (no allocation allowed) ----------------
__device__ uint4 g_Wh4[CPAD * KU4];   // W hi, [c][96] bf16 rows (k contiguous)
__device__ uint4 g_Wl4[CPAD * KU4];   // W lo
__device__ uint4 g_Xh4[NB * KU4];     // X hi, [b][96] bf16 rows
__device__ uint4 g_Xl4[NB * KU4];     // X lo
__device__ float g_A[NB * 60];        // [b][j][3x4] relative transforms
__device__ float g_JS[15 * 51];       // [j*3+k][l] joint-regressor contraction

__device__ __forceinline__ uint32_t smem_u32(const void* p) {
    uint32_t a;
    asm("{ .reg .u64 t; cvta.to.shared.u64 t, %1; cvt.u32.u64 %0, t; }"
        : "=r"(a) : "l"(p));
    return a;
}

__device__ __forceinline__ void split_bf16(float x, __nv_bfloat16& h, __nv_bfloat16& l) {
    h = __float2bfloat16_rn(x);
    l = __float2bfloat16_rn(x - __bfloat162float(h));
}

#define LDMATRIX_X4(r0, r1, r2, r3, addr) \
    asm volatile("ldmatrix.sync.aligned.m8n8.x4.shared.b16 {%0,%1,%2,%3}, [%4];" \
        : "=r"(r0), "=r"(r1), "=r"(r2), "=r"(r3) : "r"(addr))

#define MMA_BF16(c, a0, a1, a2, a3, b0, b1) \
    asm volatile("mma.sync.aligned.m16n8k16.row.col.f32.bf16.bf16.f32 " \
        "{%0,%1,%2,%3}, {%4,%5,%6,%7}, {%8,%9}, {%0,%1,%2,%3};" \
        : "+f"((c)[0]), "+f"((c)[1]), "+f"((c)[2]), "+f"((c)[3]) \
        : "r"(a0), "r"(a1), "r"(a2), "r"(a3), "r"(b0), "r"(b1))

// ---------------------------------------------------------------- pack W
__global__ void packW_kernel(const float* __restrict__ vt,
                             const float* __restrict__ SD,
                             const float* __restrict__ PD) {
    int idx = blockIdx.x * blockDim.x + threadIdx.x;   // (c, u)
    if (idx >= CPAD * KU4) return;
    int c = idx / KU4, u = idx - c * KU4;
    __nv_bfloat16 h8[8], l8[8];
    #pragma unroll
    for (int e = 0; e < 8; e++) {
        int k = u * 8 + e;
        float w = 0.f;
        if (c < NC) {
            if (k < 50)       w = SD[c * 150 + 100 + k];
            else if (k < 86)  w = PD[(k - 50) * NC + c];
            else if (k == 86) w = vt[c];
        }
        split_bf16(w, h8[e], l8[e]);
    }
    g_Wh4[idx] = *reinterpret_cast<uint4*>(h8);
    g_Wl4[idx] = *reinterpret_cast<uint4*>(l8);
}

// -------------------------------------------- J_regressor contractions
__global__ void jpre_kernel(const float* __restrict__ Jreg,
                            const float* __restrict__ vt,
                            const float* __restrict__ SD) {
    int gw = (blockIdx.x * blockDim.x + threadIdx.x) >> 5;
    int lane = threadIdx.x & 31;
    if (gw >= 765) return;
    int e = gw / 51, l = gw % 51;
    int j = e / 3, k = e % 3;
    float acc = 0.f;
    for (int v = lane; v < NV; v += 32) {
        float w = Jreg[j * NV + v];
        float s = (l < 50) ? SD[(v * 3 + k) * 150 + 100 + l] : vt[v * 3 + k];
        acc = fmaf(w, s, acc);
    }
    #pragma unroll
    for (int o = 16; o; o >>= 1) acc += __shfl_xor_sync(0xffffffffu, acc, o);
    if (lane == 0) g_JS[e * 51 + l] = acc;
}

// ------------------------------------- per-batch: rodrigues, FK, A, X rows
__global__ void batch_kernel(const float* __restrict__ expr,
                             const float* __restrict__ pose,
                             float* __restrict__ out_pf,
                             float* __restrict__ out_A) {
    int b = blockIdx.x * blockDim.x + threadIdx.x;
    if (b >= NB) return;

    __nv_bfloat16 xh[96], xl[96];
    #pragma unroll
    for (int k = 0; k < 96; k++) { xh[k] = __float2bfloat16_rn(0.f); xl[k] = xh[k]; }

    float jnt[15];
    #pragma unroll
    for (int e = 0; e < 15; e++) jnt[e] = g_JS[e * 51 + 50];
    #pragma unroll 1
    for (int l = 0; l < 50; l++) {
        float ev = expr[b * 50 + l];
        split_bf16(ev, xh[l], xl[l]);
        #pragma unroll
        for (int e = 0; e < 15; e++) jnt[e] = fmaf(ev, g_JS[e * 51 + l], jnt[e]);
    }
    split_bf16(1.f, xh[86], xl[86]);

    // Rodrigues (mirrors reference: angle uses rot_vec + 1e-8)
    float R[5][9];
    #pragma unroll
    for (int j = 0; j < 5; j++) {
        float x = pose[b * 15 + j * 3 + 0];
        float y = pose[b * 15 + j * 3 + 1];
        float z = pose[b * 15 + j * 3 + 2];
        float ax = x + 1e-8f, ay = y + 1e-8f, az = z + 1e-8f;
        float ang = sqrtf(ax * ax + ay * ay + az * az);
        float inv = 1.f / ang;
        float rx = x * inv, ry = y * inv, rz = z * inv;
        float s = sinf(ang), cth = cosf(ang), t = 1.f - cth;
        float s2 = rx * rx + ry * ry + rz * rz;
        R[j][0] = 1.f + t * (rx * rx - s2);
        R[j][1] = -s * rz + t * rx * ry;
        R[j][2] =  s * ry + t * rx * rz;
        R[j][3] =  s * rz + t * rx * ry;
        R[j][4] = 1.f + t * (ry * ry - s2);
        R[j][5] = -s * rx + t * ry * rz;
        R[j][6] = -s * ry + t * rx * rz;
        R[j][7] =  s * rx + t * ry * rz;
        R[j][8] = 1.f + t * (rz * rz - s2);
    }

    #pragma unroll
    for (int j = 1; j < 5; j++)
        #pragma unroll
        for (int idx = 0; idx < 9; idx++) {
            int m = (j - 1) * 9 + idx;
            float v = R[j][idx] - ((idx == 0 || idx == 4 || idx == 8) ? 1.f : 0.f);
            split_bf16(v, xh[50 + m], xl[50 + m]);
            out_pf[b * 36 + m] = v;
        }

    const uint4* xh4 = reinterpret_cast<const uint4*>(xh);
    const uint4* xl4 = reinterpret_cast<const uint4*>(xl);
    #pragma unroll
    for (int u = 0; u < KU4; u++) { g_Xh4[b * KU4 + u] = xh4[u]; g_Xl4[b * KU4 + u] = xl4[u]; }

    // FK chain, parents = [-1,0,1,1,1]
    float G[5][12];
    #pragma unroll
    for (int p = 0; p < 3; p++) {
        G[0][p * 4 + 0] = R[0][p * 3 + 0];
        G[0][p * 4 + 1] = R[0][p * 3 + 1];
        G[0][p * 4 + 2] = R[0][p * 3 + 2];
        G[0][p * 4 + 3] = jnt[p];
    }
    #pragma unroll
    for (int j = 1; j < 5; j++) {
        const int par = (j == 1) ? 0 : 1;
        float t0 = jnt[j * 3 + 0] - jnt[par * 3 + 0];
        float t1 = jnt[j * 3 + 1] - jnt[par * 3 + 1];
        float t2 = jnt[j * 3 + 2] - jnt[par * 3 + 2];
        #pragma unroll
        for (int p = 0; p < 3; p++) {
            float g0 = G[par][p * 4 + 0], g1 = G[par][p * 4 + 1];
            float g2 = G[par][p * 4 + 2], g3 = G[par][p * 4 + 3];
            #pragma unroll
            for (int q = 0; q < 3; q++)
                G[j][p * 4 + q] = g0 * R[j][q] + g1 * R[j][3 + q] + g2 * R[j][6 + q];
            G[j][p * 4 + 3] = g0 * t0 + g1 * t1 + g2 * t2 + g3;
        }
    }
    #pragma unroll
    for (int j = 0; j < 5; j++) {
        #pragma unroll
        for (int p = 0; p < 3; p++) {
            float r0 = G[j][p * 4 + 0], r1 = G[j][p * 4 + 1], r2 = G[j][p * 4 + 2];
            float ta = G[j][p * 4 + 3] -
                       (r0 * jnt[j * 3 + 0] + r1 * jnt[j * 3 + 1] + r2 * jnt[j * 3 + 2]);
            int gb = b * 60 + j * 12 + p * 4;
            g_A[gb + 0] = r0; g_A[gb + 1] = r1; g_A[gb + 2] = r2; g_A[gb + 3] = ta;
            int ob = b * 80 + j * 16 + p * 4;
            out_A[ob + 0] = r0; out_A[ob + 1] = r1; out_A[ob + 2] = r2; out_A[ob + 3] = ta;
        }
        int ob = b * 80 + j * 16 + 12;
        out_A[ob + 0] = 0.f; out_A[ob + 1] = 0.f; out_A[ob + 2] = 0.f; out_A[ob + 3] = 1.f;
    }
}

// =============== HMMA GEMM (128x96x96, bf16 hi/lo x3) + fused LBS ===============
// smem rows padded to 104 bf16 (208B): conflict-free ldmatrix.
static constexpr int LDB = 208;          // bytes per row
static constexpr int SM_XH = 0;
static constexpr int SM_XL = SM_XH + 128 * LDB;   // 26624
static constexpr int SM_WH = SM_XL + 128 * LDB;   // 53248
static constexpr int SM_WL = SM_WH + 96 * LDB;    // 73216
static constexpr int SM_TOTAL = SM_WL + 96 * LDB; // 93184
// epilogue overlays:
static constexpr int SM_DS = 0;          // float[128][100] = 51200 B
static constexpr int SM_AS = SM_WH;      // float[128][60]  = 30720 B
static constexpr int SM_WJ = SM_WH + 30720;  // float[160]
static constexpr int LDD = 100;          // D stride in floats

__global__ __launch_bounds__(256)
void skin_kernel(const float* __restrict__ lbs, float* __restrict__ out) {
    extern __shared__ char sm[];
    const uint32_t smb = smem_u32(sm);
    const int tid = threadIdx.x;
    const int wid = tid >> 5, lane = tid & 31;
    const int bBase = blockIdx.y * 128;
    const int cTile = blockIdx.x;          // 96 comps = 32 vertices
    const int vBase = cTile * 32;

    // ---- tile copy: global (k-contiguous rows) -> smem (stride 208B) ----
    #pragma unroll 1
    for (int i = tid; i < 128 * KU4; i += 256) {
        int r = i / KU4, u = i - r * KU4;
        uint32_t off = r * LDB + u * 16;
        int g = (bBase + r) * KU4 + u;
        *reinterpret_cast<uint4*>(sm + SM_XH + off) = g_Xh4[g];
        *reinterpret_cast<uint4*>(sm + SM_XL + off) = g_Xl4[g];
    }
    #pragma unroll 1
    for (int i = tid; i < 96 * KU4; i += 256) {
        int r = i / KU4, u = i - r * KU4;
        uint32_t off = r * LDB + u * 16;
        int g = (cTile * 96 + r) * KU4 + u;
        *reinterpret_cast<uint4*>(sm + SM_WH + off) = g_Wh4[g];
        *reinterpret_cast<uint4*>(sm + SM_WL + off) = g_Wl4[g];
    }
    __syncthreads();

    // ---- warp tile: 32 rows (2x m16) x 48 cols (6x n8) ----
    const int wm = wid & 3, wn = wid >> 2;
    float acc[2][6][4];
    #pragma unroll
    for (int mi = 0; mi < 2; mi++)
        #pragma unroll
        for (int ni = 0; ni < 6; ni++)
            #pragma unroll
            for (int e = 0; e < 4; e++) acc[mi][ni][e] = 0.f;

    // ldmatrix lane addressing (non-trans for both operands)
    const int a_row = wm * 32 + (lane & 7) + (lane & 8);
    const uint32_t a_off = a_row * LDB + ((lane >> 4) * 8) * 2;
    const int b_row = wn * 48 + ((lane >> 4) << 3) + (lane & 7);
    const uint32_t b_off = b_row * LDB + (((lane >> 3) & 1) * 8) * 2;

    #pragma unroll 1
    for (int pass = 0; pass < 3; pass++) {
        const uint32_t xb = smb + ((pass == 2) ? SM_XL : SM_XH) + a_off;
        const uint32_t wb = smb + ((pass == 1) ? SM_WL : SM_WH) + b_off;
        #pragma unroll
        for (int k = 0; k < 6; k++) {
            uint32_t a[2][4];
            LDMATRIX_X4(a[0][0], a[0][1], a[0][2], a[0][3], xb + k * 32);
            LDMATRIX_X4(a[1][0], a[1][1], a[1][2], a[1][3], xb + 16 * LDB + k * 32);
            uint32_t bfr[3][4];
            #pragma unroll
            for (int n2 = 0; n2 < 3; n2++)
                LDMATRIX_X4(bfr[n2][0], bfr[n2][1], bfr[n2][2], bfr[n2][3],
                            wb + n2 * 16 * LDB + k * 32);
            #pragma unroll
            for (int mi = 0; mi < 2; mi++)
                #pragma unroll
                for (int ni = 0; ni < 6; ni++)
                    MMA_BF16(acc[mi][ni], a[mi][0], a[mi][1], a[mi][2], a[mi][3],
                             bfr[ni >> 1][(ni & 1) * 2], bfr[ni >> 1][(ni & 1) * 2 + 1]);
        }
    }
    __syncthreads();

    // ---- stage D to smem + load A transforms + lbs weights ----
    float* Ds = reinterpret_cast<float*>(sm + SM_DS);
    #pragma unroll
    for (int mi = 0; mi < 2; mi++)
        #pragma unroll
        for (int ni = 0; ni < 6; ni++) {
            int row = wm * 32 + mi * 16 + (lane >> 2);
            int col = wn * 48 + ni * 8 + (lane & 3) * 2;
            *reinterpret_cast<float2*>(Ds + row * LDD + col) =
                make_float2(acc[mi][ni][0], acc[mi][ni][1]);
            *reinterpret_cast<float2*>(Ds + (row + 8) * LDD + col) =
                make_float2(acc[mi][ni][2], acc[mi][ni][3]);
        }
    float4* As4 = reinterpret_cast<float4*>(sm + SM_AS);
    const float4* gA4 = reinterpret_cast<const float4*>(g_A);
    #pragma unroll 1
    for (int i = tid; i < 128 * 15; i += 256) As4[i] = gA4[bBase * 15 + i];
    float* wjs = reinterpret_cast<float*>(sm + SM_WJ);
    if (tid < 160)
        wjs[tid] = (vBase + tid / 5 < NV) ? lbs[vBase * 5 + tid] : 0.f;
    __syncthreads();

    // ---- fused LBS skinning epilogue ----
    const float* As = reinterpret_cast<const float*>(sm + SM_AS);
    float wt[5];
    #pragma unroll
    for (int j = 0; j < 5; j++) wt[j] = wjs[lane * 5 + j];
    const int v = vBase + lane;
    if (v < NV) {
        #pragma unroll 1
        for (int i = 0; i < 16; i++) {
            const int bl = wid + 8 * i;
            const float4* Ab4 = reinterpret_cast<const float4*>(As + bl * 60);
            float4 M0 = make_float4(0.f, 0.f, 0.f, 0.f), M1 = M0, M2 = M0;
            #pragma unroll
            for (int j = 0; j < 5; j++) {
                float wv = wt[j];
                float4 a0 = Ab4[j * 3 + 0], a1 = Ab4[j * 3 + 1], a2 = Ab4[j * 3 + 2];
                M0.x = fmaf(wv, a0.x, M0.x); M0.y = fmaf(wv, a0.y, M0.y);
                M0.z = fmaf(wv, a0.z, M0.z); M0.w = fmaf(wv, a0.w, M0.w);
                M1.x = fmaf(wv, a1.x, M1.x); M1.y = fmaf(wv, a1.y, M1.y);
                M1.z = fmaf(wv, a1.z, M1.z); M1.w = fmaf(wv, a1.w, M1.w);
                M2.x = fmaf(wv, a2.x, M2.x); M2.y = fmaf(wv, a2.y, M2.y);
                M2.z = fmaf(wv, a2.z, M2.z); M2.w = fmaf(wv, a2.w, M2.w);
            }
            const float* Dr = Ds + bl * LDD + lane * 3;
            float px = Dr[0], py = Dr[1], pz = Dr[2];
            size_t ob = ((size_t)(bBase + bl) * NV + v) * 3;
            out[ob + 0] = fmaf(M0.x, px, fmaf(M0.y, py, fmaf(M0.z, pz, M0.w)));
            out[ob + 1] = fmaf(M1.x, px, fmaf(M1.y, py, fmaf(M1.z, pz, M1.w)));
            out[ob + 2] = fmaf(M2.x, px, fmaf(M2.y, py, fmaf(M2.z, pz, M2.w)));
        }
    }
}

// ---------------------------------------------------------------- launch
extern "C" void kernel_launch(void* const* d_in, const int* in_sizes, int n_in,
                              void* d_out, int out_size) {
    const float* expr = (const float*)d_in[0];  // [2048,50]
    const float* pose = (const float*)d_in[1];  // [2048,15]
    const float* vt   = (const float*)d_in[2];  // [5023,3]
    const float* SD   = (const float*)d_in[3];  // [5023,3,150]
    const float* PD   = (const float*)d_in[4];  // [36,15069]
    const float* Jreg = (const float*)d_in[5];  // [5,5023]
    const float* lbs  = (const float*)d_in[6];  // [5023,5]

    float* out       = (float*)d_out;
    float* out_verts = out;                       // [B,V,3]
    float* out_pf    = out + (size_t)NB * NV * 3; // [B,36]
    float* out_A     = out_pf + (size_t)NB * 36;  // [B,5,4,4]

    cudaFuncSetAttribute(skin_kernel,
                         cudaFuncAttributeMaxDynamicSharedMemorySize, SM_TOTAL);

    packW_kernel<<<(CPAD * KU4 + 255) / 256, 256>>>(vt, SD, PD);
    jpre_kernel<<<(765 * 32 + 255) / 256, 256>>>(Jreg, vt, SD);
    batch_kernel<<<NB / 128, 128>>>(expr, pose, out_pf, out_A);
    dim3 grid(157, 16);
    skin_kernel<<<grid, 256, SM_TOTAL>>>(lbs, out_verts);
}